// round 3
// baseline (speedup 1.0000x reference)
#include <cuda_runtime.h>

// Shapes (fixed by the problem): B=8, C=128, H=256, W=256
#define B_   8
#define C_   128
#define H_   256
#define W_   256
#define HW_  (H_ * W_)            // 65536
#define CHW_ (C_ * HW_)           // 8388608 = 2^23
#define NPIX (B_ * HW_)           // 524288
#define NELEM (B_ * CHW_)         // 67108864

// Scratch (allocation-free per harness rules)
__device__ float g_pooled[NPIX];  // 2 MB, [b][h][w]
__device__ float g_attn[NPIX];    // 2 MB, [b][h][w]

// ---------------------------------------------------------------------------
// Pass 1: pooled[b,hw] = max_c x[b,c,hw].  One thread = 4 consecutive w.
// 128 independent float4 loads per thread (stride 16384 float4s); pure stream.
// ---------------------------------------------------------------------------
__global__ void __launch_bounds__(256) pool_max_kernel(const float* __restrict__ x) {
    unsigned t  = blockIdx.x * 256u + threadIdx.x;   // [0, NPIX/4)
    unsigned p4 = t << 2;                            // pixel index (multiple of 4)
    unsigned b  = p4 >> 16;                          // p4 / HW_
    unsigned hw = p4 & 65535u;

    const float4* base = reinterpret_cast<const float4*>(x + (size_t)b * CHW_ + hw);
    const unsigned cstride = HW_ / 4;                // 16384 float4s per channel

    float4 m = __ldg(base);
#pragma unroll 8
    for (int c = 1; c < C_; ++c) {
        float4 v = __ldg(base + (size_t)c * cstride);
        m.x = fmaxf(m.x, v.x);
        m.y = fmaxf(m.y, v.y);
        m.z = fmaxf(m.z, v.z);
        m.w = fmaxf(m.w, v.w);
    }
    reinterpret_cast<float4*>(g_pooled)[t] = m;
}

// ---------------------------------------------------------------------------
// Pass 2: attn = sigmoid(conv7x7(pooled) + bias).  One thread = 4 pixels.
// pooled (2 MB) is L2-resident; 70 cached loads + 196 FMA per thread. Tiny.
// ---------------------------------------------------------------------------
__global__ void __launch_bounds__(256) conv_sigmoid_kernel(
    const float* __restrict__ wgt, const float* __restrict__ bias) {
    __shared__ float sw[49];
    if (threadIdx.x < 49) sw[threadIdx.x] = wgt[threadIdx.x];
    __syncthreads();

    unsigned t  = blockIdx.x * 256u + threadIdx.x;   // [0, NPIX/4)
    unsigned p4 = t << 2;
    unsigned b  = p4 >> 16;
    unsigned hw = p4 & 65535u;
    int h = (int)(hw >> 8);
    int w = (int)(hw & 255u);                        // multiple of 4

    const float* pb = g_pooled + (size_t)b * HW_;
    float bv = __ldg(bias);
    float a0 = bv, a1 = bv, a2 = bv, a3 = bv;

#pragma unroll
    for (int kh = 0; kh < 7; ++kh) {
        int hh = h + kh - 3;
        if ((unsigned)hh < (unsigned)H_) {
            const float* row = pb + hh * W_;
            float r[10];
#pragma unroll
            for (int i = 0; i < 10; ++i) {
                int cc = w - 3 + i;
                r[i] = ((unsigned)cc < (unsigned)W_) ? __ldg(row + cc) : 0.0f;
            }
#pragma unroll
            for (int kw = 0; kw < 7; ++kw) {
                float wv = sw[kh * 7 + kw];
                a0 = fmaf(r[kw + 0], wv, a0);
                a1 = fmaf(r[kw + 1], wv, a1);
                a2 = fmaf(r[kw + 2], wv, a2);
                a3 = fmaf(r[kw + 3], wv, a3);
            }
        }
    }

    float4 a;
    a.x = 1.0f / (1.0f + __expf(-a0));
    a.y = 1.0f / (1.0f + __expf(-a1));
    a.z = 1.0f / (1.0f + __expf(-a2));
    a.w = 1.0f / (1.0f + __expf(-a3));
    reinterpret_cast<float4*>(g_attn)[t] = a;
}

// ---------------------------------------------------------------------------
// Pass 3: out[e] = x[e] * attn[pixel(e)].  One thread = one float4.
// pixel index from element index e: b = e>>23, hw = e & 0xFFFF.
// attn (2 MB) stays in L2 across the whole kernel -> only input+output hit DRAM.
// ---------------------------------------------------------------------------
__global__ void __launch_bounds__(256) bcast_mul_kernel(
    const float* __restrict__ x, float* __restrict__ out) {
    unsigned t = blockIdx.x * 256u + threadIdx.x;    // [0, NELEM/4)
    unsigned e = t << 2;                             // element index
    unsigned p = ((e >> 23) << 16) | (e & 65535u);   // b*HW_ + hw

    float4 v = reinterpret_cast<const float4*>(x)[t];
    float4 a = *reinterpret_cast<const float4*>(g_attn + p);
    v.x *= a.x;
    v.y *= a.y;
    v.z *= a.z;
    v.w *= a.w;
    reinterpret_cast<float4*>(out)[t] = v;
}

// ---------------------------------------------------------------------------
extern "C" void kernel_launch(void* const* d_in, const int* in_sizes, int n_in,
                              void* d_out, int out_size) {
    const float* x      = (const float*)d_in[0];   // [8,128,256,256] fp32
    const float* conv_w = (const float*)d_in[1];   // [1,1,7,7] fp32
    const float* conv_b = (const float*)d_in[2];   // [1] fp32
    float* out = (float*)d_out;

    // Pass 1: 524288 pixels / 4 per thread = 131072 threads
    pool_max_kernel<<<NPIX / 4 / 256, 256>>>(x);
    // Pass 2: same geometry
    conv_sigmoid_kernel<<<NPIX / 4 / 256, 256>>>(conv_w, conv_b);
    // Pass 3: 67108864 elems / 4 per thread = 16777216 threads
    bcast_mul_kernel<<<NELEM / 4 / 256, 256>>>(x, out);
}

// round 5
// speedup vs baseline: 1.0147x; 1.0147x over previous
#include <cuda_runtime.h>

// Shapes (fixed): B=8, C=128, H=256, W=256
#define B_    8
#define C_    128
#define H_    256
#define W_    256
#define HW_   (H_ * W_)            // 65536
#define CHW_  (C_ * HW_)           // 8388608 = 2^23
#define NPIX  (B_ * HW_)           // 524288
#define NELEM (B_ * CHW_)          // 67108864
#define HW4   (HW_ / 4)            // 16384 float4 per (b, channel) plane

// Scratch (allocation-free per harness rules)
__device__ float g_part0[NPIX];    // 2 MB, channel-max over c in [0,64)
__device__ float g_part1[NPIX];    // 2 MB, channel-max over c in [64,128)
__device__ float g_attn[NPIX];     // 2 MB

// ---------------------------------------------------------------------------
// Pass 1: partial channel max. 2-way channel split for 2x occupancy.
// Thread t: half = t>>17 (c in [half*64, half*64+64)), pix4 = t & 131071.
// 64 independent float4 loads (stride 64KB); unroll 8 batches them for MLP.
// ---------------------------------------------------------------------------
__global__ void __launch_bounds__(256) pool_max_kernel(const float* __restrict__ x) {
    unsigned t    = blockIdx.x * 256u + threadIdx.x;   // [0, 2*NPIX/4)
    unsigned pix4 = t & 131071u;                       // [0, NPIX/4)
    unsigned half = t >> 17;                           // 0 or 1
    unsigned b    = pix4 >> 14;                        // pix4 / HW4
    unsigned hw4  = pix4 & 16383u;

    const float4* base = reinterpret_cast<const float4*>(x)
                       + (size_t)b * (CHW_ / 4) + (size_t)half * 64u * HW4 + hw4;

    float4 m = __ldg(base);
#pragma unroll 8
    for (int c = 1; c < 64; ++c) {
        float4 v = __ldg(base + (size_t)c * HW4);
        m.x = fmaxf(m.x, v.x);
        m.y = fmaxf(m.y, v.y);
        m.z = fmaxf(m.z, v.z);
        m.w = fmaxf(m.w, v.w);
    }
    float4* dst = half ? reinterpret_cast<float4*>(g_part1)
                       : reinterpret_cast<float4*>(g_part0);
    dst[pix4] = m;
}

// ---------------------------------------------------------------------------
// Pass 2: attn = sigmoid(conv7x7(max(part0,part1)) + bias). 4 pixels/thread.
// Partials (4 MB) are L2-resident; tiny kernel.
// ---------------------------------------------------------------------------
__global__ void __launch_bounds__(256) conv_sigmoid_kernel(
    const float* __restrict__ wgt, const float* __restrict__ bias) {
    __shared__ float sw[49];
    if (threadIdx.x < 49) sw[threadIdx.x] = wgt[threadIdx.x];
    __syncthreads();

    unsigned t  = blockIdx.x * 256u + threadIdx.x;   // [0, NPIX/4)
    unsigned p4 = t << 2;
    unsigned b  = p4 >> 16;
    unsigned hw = p4 & 65535u;
    int h = (int)(hw >> 8);
    int w = (int)(hw & 255u);                        // multiple of 4

    const float* p0 = g_part0 + (size_t)b * HW_;
    const float* p1 = g_part1 + (size_t)b * HW_;
    float bv = __ldg(bias);
    float a0 = bv, a1 = bv, a2 = bv, a3 = bv;

#pragma unroll
    for (int kh = 0; kh < 7; ++kh) {
        int hh = h + kh - 3;
        if ((unsigned)hh < (unsigned)H_) {
            int roff = hh * W_;
            float r[10];
#pragma unroll
            for (int i = 0; i < 10; ++i) {
                int cc = w - 3 + i;
                r[i] = ((unsigned)cc < (unsigned)W_)
                         ? fmaxf(__ldg(p0 + roff + cc), __ldg(p1 + roff + cc))
                         : 0.0f;
            }
#pragma unroll
            for (int kw = 0; kw < 7; ++kw) {
                float wv = sw[kh * 7 + kw];
                a0 = fmaf(r[kw + 0], wv, a0);
                a1 = fmaf(r[kw + 1], wv, a1);
                a2 = fmaf(r[kw + 2], wv, a2);
                a3 = fmaf(r[kw + 3], wv, a3);
            }
        }
    }

    float4 a;
    a.x = 1.0f / (1.0f + __expf(-a0));
    a.y = 1.0f / (1.0f + __expf(-a1));
    a.z = 1.0f / (1.0f + __expf(-a2));
    a.w = 1.0f / (1.0f + __expf(-a3));
    reinterpret_cast<float4*>(g_attn)[t] = a;
}

// ---------------------------------------------------------------------------
// Pass 3: out = x * attn, 8 channels per thread for one pixel-quad.
// attn loaded ONCE per thread (L2 traffic /8 vs 1-channel version).
// x/out streamed with .cs hints; 8 batched loads give MLP=8.
// ---------------------------------------------------------------------------
__global__ void __launch_bounds__(256) bcast_mul_kernel(
    const float* __restrict__ x, float* __restrict__ out) {
    unsigned t   = blockIdx.x * 256u + threadIdx.x;  // [0, NELEM/4/8) = [0, 2097152)
    unsigned hw4 = t & 16383u;
    unsigned cg  = (t >> 14) & 15u;                  // channel group, 8 ch each
    unsigned b   = t >> 18;

    size_t base = (size_t)b * (CHW_ / 4) + (size_t)cg * 8u * HW4 + hw4;
    const float4* xp = reinterpret_cast<const float4*>(x) + base;
    float4*       op = reinterpret_cast<float4*>(out) + base;

    float4 a = *(reinterpret_cast<const float4*>(g_attn) + (size_t)b * HW4 + hw4);

    float4 v[8];
#pragma unroll
    for (int c = 0; c < 8; ++c) v[c] = __ldcs(xp + (size_t)c * HW4);
#pragma unroll
    for (int c = 0; c < 8; ++c) {
        float4 r;
        r.x = v[c].x * a.x;
        r.y = v[c].y * a.y;
        r.z = v[c].z * a.z;
        r.w = v[c].w * a.w;
        __stcs(op + (size_t)c * HW4, r);
    }
}

// ---------------------------------------------------------------------------
extern "C" void kernel_launch(void* const* d_in, const int* in_sizes, int n_in,
                              void* d_out, int out_size) {
    const float* x      = (const float*)d_in[0];   // [8,128,256,256] fp32
    const float* conv_w = (const float*)d_in[1];   // [1,1,7,7] fp32
    const float* conv_b = (const float*)d_in[2];   // [1] fp32
    float* out = (float*)d_out;

    // Pass 1: 2 * NPIX/4 threads = 262144 -> 1024 blocks
    pool_max_kernel<<<2 * (NPIX / 4) / 256, 256>>>(x);
    // Pass 2: NPIX/4 threads -> 512 blocks
    conv_sigmoid_kernel<<<(NPIX / 4) / 256, 256>>>(conv_w, conv_b);
    // Pass 3: NELEM/4/8 threads = 2097152 -> 8192 blocks
    bcast_mul_kernel<<<(NELEM / 4 / 8) / 256, 256>>>(x, out);
}